// round 17
// baseline (speedup 1.0000x reference)
#include <cuda_runtime.h>
#include <cuda_fp16.h>
#include <cstdint>

#define DMODEL 1024
#define NHEADS 16
#define DK 64
#define BATCH 2
#define SEQ 2048
#define MK (BATCH * SEQ * DMODEL)   // 4194304
#define DD (DMODEL * DMODEL)        // 1048576

// Scratch (allocation-free)
__device__ __half g_qh[MK];                  // Q fp16, pre-scaled by 0.125*log2(e)
__device__ __half g_kh[MK];                  // K fp16
__device__ __half g_vh[MK], g_vl[MK];        // V fp16 hi/lo
__device__ __half g_xh[3][MK], g_xl[3][MK];  // gemm inputs fp16 hi/lo
__device__ __half g_w[4][DD];                // weights fp16 (single)
__device__ __half g_ch2[MK], g_cl2[MK];      // ctx fp16 hi/lo
__device__ uint32_t g_mbits[BATCH * SEQ * (SEQ / 32)];  // packed mask, 1 MB

__device__ __forceinline__ uint32_t smem_u32(const void* p) {
    uint32_t a;
    asm("{ .reg .u64 t; cvta.to.shared.u64 t, %1; cvt.u32.u64 %0, t; }"
        : "=r"(a) : "l"(p));
    return a;
}
__device__ __forceinline__ float ex2f(float x) {
    float r;
    asm("ex2.approx.f32 %0, %1;" : "=f"(r) : "f"(x));
    return r;
}
// Pack two fp32 into one fp16x2 register: lo half = a, hi half = b.
__device__ __forceinline__ uint32_t pack_f16x2(float a, float b) {
    uint32_t r;
    asm("cvt.rn.f16x2.f32 %0, %1, %2;" : "=r"(r) : "f"(b), "f"(a));
    return r;
}

#define LDSM_X4(r0, r1, r2, r3, addr) \
    asm volatile("ldmatrix.sync.aligned.m8n8.x4.shared.b16 {%0,%1,%2,%3}, [%4];" \
                 : "=r"(r0), "=r"(r1), "=r"(r2), "=r"(r3) : "r"(addr))
#define LDSM_X4_T(r0, r1, r2, r3, addr) \
    asm volatile("ldmatrix.sync.aligned.m8n8.x4.trans.shared.b16 {%0,%1,%2,%3}, [%4];" \
                 : "=r"(r0), "=r"(r1), "=r"(r2), "=r"(r3) : "r"(addr))
#define MMA16816H(c, a, b0, b1) \
    asm volatile("mma.sync.aligned.m16n8k16.row.col.f32.f16.f16.f32 " \
                 "{%0,%1,%2,%3}, {%4,%5,%6,%7}, {%8,%9}, {%0,%1,%2,%3};" \
                 : "+f"((c)[0]), "+f"((c)[1]), "+f"((c)[2]), "+f"((c)[3]) \
                 : "r"((a)[0]), "r"((a)[1]), "r"((a)[2]), "r"((a)[3]), \
                   "r"(b0), "r"(b1))
#define CP_ASYNC16(dst, src) \
    asm volatile("cp.async.cg.shared.global [%0], [%1], 16;" :: "r"(dst), "l"(src))
#define CP_COMMIT() asm volatile("cp.async.commit_group;" ::: "memory")
#define CP_WAIT2()  asm volatile("cp.async.wait_group 2;" ::: "memory")
#define CP_WAIT1()  asm volatile("cp.async.wait_group 1;" ::: "memory")
#define CP_WAIT0()  asm volatile("cp.async.wait_group 0;" ::: "memory")

// Split 8 floats into fp16 hi/lo
__device__ __forceinline__ void cvt8_f16_hl(unsigned short* hi, unsigned short* lo,
                                            float4 x, float4 y) {
    float f[8] = {x.x, x.y, x.z, x.w, y.x, y.y, y.z, y.w};
    uint32_t hp[4], lp[4];
    #pragma unroll
    for (int j = 0; j < 4; j++) {
        __half h0 = __float2half_rn(f[2 * j]);
        __half h1 = __float2half_rn(f[2 * j + 1]);
        float r0 = f[2 * j]     - __half2float(h0);
        float r1 = f[2 * j + 1] - __half2float(h1);
        __half l0 = __float2half_rn(r0);
        __half l1 = __float2half_rn(r1);
        hp[j] = (uint32_t)__half_as_ushort(h0) | ((uint32_t)__half_as_ushort(h1) << 16);
        lp[j] = (uint32_t)__half_as_ushort(l0) | ((uint32_t)__half_as_ushort(l1) << 16);
    }
    *(uint4*)hi = make_uint4(hp[0], hp[1], hp[2], hp[3]);
    *(uint4*)lo = make_uint4(lp[0], lp[1], lp[2], lp[3]);
}
__device__ __forceinline__ void cvt8_f16(unsigned short* dst, float4 x, float4 y) {
    float f[8] = {x.x, x.y, x.z, x.w, y.x, y.y, y.z, y.w};
    uint32_t hp[4];
    #pragma unroll
    for (int j = 0; j < 4; j++) {
        __half h0 = __float2half_rn(f[2 * j]);
        __half h1 = __float2half_rn(f[2 * j + 1]);
        hp[j] = (uint32_t)__half_as_ushort(h0) | ((uint32_t)__half_as_ushort(h1) << 16);
    }
    *(uint4*)dst = make_uint4(hp[0], hp[1], hp[2], hp[3]);
}
__device__ __forceinline__ void cvt_pfrag(float p0, float p1, uint32_t& hi, uint32_t& lo) {
    __half h0 = __float2half_rn(p0), h1 = __float2half_rn(p1);
    float r0 = p0 - __half2float(h0), r1 = p1 - __half2float(h1);
    __half g0 = __float2half_rn(r0), g1 = __float2half_rn(r1);
    hi = (uint32_t)__half_as_ushort(h0) | ((uint32_t)__half_as_ushort(h1) << 16);
    lo = (uint32_t)__half_as_ushort(g0) | ((uint32_t)__half_as_ushort(g1) << 16);
}

// ---------------------------------------------------------------------------
// Fused pre-convert + mask pack, one launch.
// ---------------------------------------------------------------------------
#define XN8 (MK / 8)   // 524288
#define WN8 (DD / 8)   // 131072
#define CVT_T (3 * XN8 + 4 * WN8)          // 2097152
#define MSK_T (BATCH * SEQ * SEQ)          // 8388608
#define ALL_T (CVT_T + MSK_T)

__global__ void cvt_all(const float* __restrict__ q, const float* __restrict__ k,
                        const float* __restrict__ v, const float* __restrict__ Wq,
                        const float* __restrict__ Wk, const float* __restrict__ Wv,
                        const float* __restrict__ Wo, const int* __restrict__ mask)
{
    size_t i = (size_t)blockIdx.x * blockDim.x + threadIdx.x;
    if (i < 3 * (size_t)XN8) {
        int seg = (int)(i / XN8);
        size_t off = i - (size_t)seg * XN8;
        const float* src = (seg == 0) ? q : (seg == 1) ? k : v;
        float4 a = ((const float4*)src)[2 * off];
        float4 b = ((const float4*)src)[2 * off + 1];
        cvt8_f16_hl((unsigned short*)g_xh[seg] + 8 * off,
                    (unsigned short*)g_xl[seg] + 8 * off, a, b);
    } else if (i < CVT_T) {
        size_t j = i - 3 * (size_t)XN8;
        int seg = (int)(j / WN8);
        size_t off = j - (size_t)seg * WN8;
        const float* src = (seg == 0) ? Wq : (seg == 1) ? Wk : (seg == 2) ? Wv : Wo;
        float4 a = ((const float4*)src)[2 * off];
        float4 b = ((const float4*)src)[2 * off + 1];
        cvt8_f16((unsigned short*)g_w[seg] + 8 * off, a, b);
    } else {
        size_t m = i - CVT_T;   // segment start is 32-aligned
        uint32_t bal = __ballot_sync(0xffffffffu, mask[m] != 0);
        if ((threadIdx.x & 31) == 0) g_mbits[m >> 5] = bal;
    }
}

// ---------------------------------------------------------------------------
// GEMM tile core: fp16 2-pass (A hi/lo x W single), cp.async 3-stage,
// one barrier/chunk, fragment prefetch.
// MODE 0: fp32 out. MODE 1: fp16 hi/lo split-head. MODE 2: fp16 split-head.
// Stage (halves): Ah[128*40] | Al[128*40] | B[32*136]
// ---------------------------------------------------------------------------
#define ST_AL 5120
#define ST_B  10240
#define ST_SZ 14592

template <int MODE>
__device__ __forceinline__ void gemm_tile(
    const __half* __restrict__ Ah_g, const __half* __restrict__ Al_g,
    const __half* __restrict__ W_g,
    const float* __restrict__ bias, void* out0, void* out1, float oscale,
    unsigned short* smh, int m0, int n0)
{
    const int tid = threadIdx.x;
    const int warp = tid >> 5, lane = tid & 31;
    const int mw = (warp & 3) * 32, nw = (warp >> 2) * 64;

    auto issue_chunk = [&](int ch, int st) {
        unsigned short* base = smh + st * ST_SZ;
        #pragma unroll
        for (int i = 0; i < 2; i++) {
            int idx = tid + 256 * i;
            int row = idx >> 2, seg = idx & 3;
            const size_t ga = (size_t)(m0 + row) * 1024 + ch * 32 + seg * 8;
            CP_ASYNC16(smem_u32(base + row * 40 + seg * 8), Ah_g + ga);
            CP_ASYNC16(smem_u32(base + ST_AL + row * 40 + seg * 8), Al_g + ga);
            int krow = idx >> 4, nseg = idx & 15;
            const size_t gb = (size_t)(ch * 32 + krow) * 1024 + n0 + nseg * 8;
            CP_ASYNC16(smem_u32(base + ST_B + krow * 136 + nseg * 8), W_g + gb);
        }
        CP_COMMIT();
    };

    float acc[2][8][4];
    #pragma unroll
    for (int i = 0; i < 2; i++)
        #pragma unroll
        for (int j = 0; j < 8; j++)
            #pragma unroll
            for (int l = 0; l < 4; l++) acc[i][j][l] = 0.0f;

    const int aq = lane >> 3, ai = lane & 7;
    const int a_row = mw + (aq & 1) * 8 + ai;
    const int a_col = (aq >> 1) * 8;
    const int b_krow = (aq & 1) * 8 + ai;
    const int b_nc0 = nw + (aq >> 1) * 8;

    issue_chunk(0, 0);
    issue_chunk(1, 1);

    for (int ch = 0; ch < 32; ch++) {
        const int s = ch % 3;
        if (ch == 31) CP_WAIT0(); else CP_WAIT1();
        __syncthreads();
        if (ch + 2 < 32) issue_chunk(ch + 2, (ch + 2) % 3);
        unsigned short* base = smh + s * ST_SZ;

        #pragma unroll
        for (int ks = 0; ks < 2; ks++) {
            uint32_t afh[2][4], afl[2][4], bf[4][4];
            #pragma unroll
            for (int mt = 0; mt < 2; mt++) {
                uint32_t adh = smem_u32(base + (a_row + mt * 16) * 40 + ks * 16 + a_col);
                LDSM_X4(afh[mt][0], afh[mt][1], afh[mt][2], afh[mt][3], adh);
                uint32_t adl = smem_u32(base + ST_AL + (a_row + mt * 16) * 40 +
                                        ks * 16 + a_col);
                LDSM_X4(afl[mt][0], afl[mt][1], afl[mt][2], afl[mt][3], adl);
            }
            #pragma unroll
            for (int ntp = 0; ntp < 4; ntp++) {
                uint32_t bd = smem_u32(base + ST_B + (ks * 16 + b_krow) * 136 +
                                       b_nc0 + ntp * 16);
                LDSM_X4_T(bf[ntp][0], bf[ntp][1], bf[ntp][2], bf[ntp][3], bd);
            }
            #pragma unroll
            for (int ntp = 0; ntp < 4; ntp++) {
                MMA16816H(acc[0][ntp * 2],     afh[0], bf[ntp][0], bf[ntp][1]);
                MMA16816H(acc[0][ntp * 2],     afl[0], bf[ntp][0], bf[ntp][1]);
                MMA16816H(acc[0][ntp * 2 + 1], afh[0], bf[ntp][2], bf[ntp][3]);
                MMA16816H(acc[0][ntp * 2 + 1], afl[0], bf[ntp][2], bf[ntp][3]);
                MMA16816H(acc[1][ntp * 2],     afh[1], bf[ntp][0], bf[ntp][1]);
                MMA16816H(acc[1][ntp * 2],     afl[1], bf[ntp][0], bf[ntp][1]);
                MMA16816H(acc[1][ntp * 2 + 1], afh[1], bf[ntp][2], bf[ntp][3]);
                MMA16816H(acc[1][ntp * 2 + 1], afl[1], bf[ntp][2], bf[ntp][3]);
            }
        }
    }

    #pragma unroll
    for (int mt = 0; mt < 2; mt++) {
        #pragma unroll
        for (int nt = 0; nt < 8; nt++) {
            int row = m0 + mw + mt * 16 + (lane >> 2);
            int col = n0 + nw + nt * 8 + (lane & 3) * 2;
            float2 bs = *(const float2*)&bias[col];
            float* c = acc[mt][nt];
            float o00 = c[0] + bs.x, o01 = c[1] + bs.y;
            float o10 = c[2] + bs.x, o11 = c[3] + bs.y;
            if (MODE == 0) {
                float* C = (float*)out0;
                *(float2*)&C[(size_t)row * 1024 + col] = make_float2(o00, o01);
                *(float2*)&C[(size_t)(row + 8) * 1024 + col] = make_float2(o10, o11);
            } else {
                int h = col >> 6, d = col & 63;
                int b_ = row >> 11, s_ = row & 2047;
                size_t idx = (((size_t)(b_ * NHEADS + h)) * SEQ + s_) * DK + d;
                if (MODE == 1) {
                    uint32_t h32, l32;
                    cvt_pfrag(o00, o01, h32, l32);
                    *(uint32_t*)((__half*)out0 + idx) = h32;
                    *(uint32_t*)((__half*)out1 + idx) = l32;
                    cvt_pfrag(o10, o11, h32, l32);
                    *(uint32_t*)((__half*)out0 + idx + 8 * DK) = h32;
                    *(uint32_t*)((__half*)out1 + idx + 8 * DK) = l32;
                } else {
                    *(uint32_t*)((__half*)out0 + idx) =
                        pack_f16x2(o00 * oscale, o01 * oscale);
                    *(uint32_t*)((__half*)out0 + idx + 8 * DK) =
                        pack_f16x2(o10 * oscale, o11 * oscale);
                }
            }
        }
    }
}

// Q pre-scale: (1/8) * log2(e) -> QK^T scores land in log2 domain
#define QSCALE 0.180336880f

__global__ void __launch_bounds__(256, 2) qkv_gemm(
    const float* __restrict__ b0, const float* __restrict__ b1,
    const float* __restrict__ b2)
{
    extern __shared__ unsigned short smh[];
    const int z = blockIdx.z;
    if (z == 0)
        gemm_tile<2>(g_xh[0], g_xl[0], g_w[0], b0, g_qh, nullptr, QSCALE,
                     smh, blockIdx.y * 128, blockIdx.x * 128);
    else if (z == 1)
        gemm_tile<2>(g_xh[1], g_xl[1], g_w[1], b1, g_kh, nullptr, 1.0f,
                     smh, blockIdx.y * 128, blockIdx.x * 128);
    else
        gemm_tile<1>(g_xh[2], g_xl[2], g_w[2], b2, g_vh, g_vl, 1.0f,
                     smh, blockIdx.y * 128, blockIdx.x * 128);
}

__global__ void __launch_bounds__(256, 2) o_gemm(
    const float* __restrict__ bo, float* __restrict__ out)
{
    extern __shared__ unsigned short smh[];
    gemm_tile<0>(g_ch2, g_cl2, g_w[3], bo, out, nullptr, 1.0f, smh,
                 blockIdx.y * 128, blockIdx.x * 128);
}

// ---------------------------------------------------------------------------
// Tensor-core flash attention: Q,K fp16 (Q log2-prescaled), V hi/lo fp16,
// 1-pass QK, exp2-based fixed-shift softmax, P single fp16 x V hi/lo (2-pass),
// 3-stage cp.async, one barrier/tile, bitmask, occ 2.
// smem halves: Qh[9216] | stage{0,1,2}{K[4608], Vh[4608], Vl[4608]}  (101376 B)
// ---------------------------------------------------------------------------
#define FQ_SZ 9216
#define FS_VH 4608
#define FS_VL 9216
#define FS_SZ 13824
#define NKT   (SEQ / 64)   // 32
#define SHIFT2 11.5416f    // 8 * log2(e); arbitrary, cancels in O/l
#define MWORDS (SEQ / 32)

__global__ void __launch_bounds__(256, 2) flash_tc(
    const __half* __restrict__ qh_g, const __half* __restrict__ kh_g,
    const __half* __restrict__ vh_g, const __half* __restrict__ vl_g,
    __half* __restrict__ ch_g, __half* __restrict__ cl_g)
{
    extern __shared__ __align__(16) unsigned short sh[];

    const int tid = threadIdx.x;
    const int warp = tid >> 5, lane = tid & 31;
    const int b = blockIdx.z, h = blockIdx.y;
    const int q0 = blockIdx.x * 128;
    const int mw = warp * 16;

    const size_t bh = ((size_t)(b * NHEADS + h)) * SEQ * DK;
    const __half* Qh_b = qh_g + bh + (size_t)q0 * DK;
    const __half* Kh_b = kh_g + bh;
    const __half* Vh_b = vh_g + bh;
    const __half* Vl_b = vl_g + bh;

    // Q tile (group 0): 128 rows, single fp16
    #pragma unroll
    for (int it = 0; it < 4; it++) {
        int idx = tid + it * 256;
        int row = idx >> 3, seg = idx & 7;
        CP_ASYNC16(smem_u32(sh + row * 72 + seg * 8), Qh_b + (size_t)row * DK + seg * 8);
    }
    CP_COMMIT();

    auto issue_tile = [&](int kt, int st) {
        unsigned short* base = sh + FQ_SZ + st * FS_SZ;
        const size_t t0 = (size_t)(kt * 64) * DK;
        #pragma unroll
        for (int it = 0; it < 2; it++) {
            int idx = tid + it * 256;
            int row = idx >> 3, seg = idx & 7;
            size_t go = t0 + (size_t)row * DK + seg * 8;
            CP_ASYNC16(smem_u32(base + row * 72 + seg * 8), Kh_b + go);
            CP_ASYNC16(smem_u32(base + FS_VH + row * 72 + seg * 8), Vh_b + go);
            CP_ASYNC16(smem_u32(base + FS_VL + row * 72 + seg * 8), Vl_b + go);
        }
        CP_COMMIT();
    };

    issue_tile(0, 0);
    issue_tile(1, 1);

    // Q fragments (wait for Q group done -> <=2 pending)
    CP_WAIT2();
    __syncthreads();
    const int aq = lane >> 3, ai = lane & 7;
    uint32_t qhf[4][4];
    {
        int arow = mw + (aq & 1) * 8 + ai;
        int acol = (aq >> 1) * 8;
        #pragma unroll
        for (int kc = 0; kc < 4; kc++) {
            uint32_t adh = smem_u32(sh + arow * 72 + kc * 16 + acol);
            LDSM_X4(qhf[kc][0], qhf[kc][1], qhf[kc][2], qhf[kc][3], adh);
        }
    }

    const int kqr = (aq >> 1) * 8 + ai;
    const int kqc = (aq & 1) * 8;
    const int vbr = (aq & 1) * 8 + ai;
    const int vbc = (aq >> 1) * 8;

    const int r0 = lane >> 2;
    const uint32_t* mrow0 = g_mbits + (size_t)(b * SEQ + q0 + mw + r0) * MWORDS;
    const uint32_t* mrow1 = mrow0 + 8 * MWORDS;
    const int bsh = 2 * (lane & 3);

    float l0 = 0.0f, l1 = 0.0f;
    float o[8][4];
    #pragma unroll
    for (int i = 0; i < 8; i++) o[i][0] = o[i][1] = o[i][2] = o[i][3] = 0.0f;

    for (int kt = 0; kt < NKT; kt++) {
        const int st = kt % 3;
        if (kt == NKT - 1) CP_WAIT0(); else CP_WAIT1();
        __syncthreads();
        if (kt + 2 < NKT) issue_tile(kt + 2, (kt + 2) % 3);
        unsigned short* base = sh + FQ_SZ + st * FS_SZ;

        // S2 = Qs @ K^T (single pass; scores in log2 domain via Q prescale)
        float acc[8][4];
        #pragma unroll
        for (int nt = 0; nt < 8; nt++)
            acc[nt][0] = acc[nt][1] = acc[nt][2] = acc[nt][3] = 0.0f;

        #pragma unroll
        for (int kc = 0; kc < 4; kc++) {
            #pragma unroll
            for (int p = 0; p < 4; p++) {
                uint32_t b0, b1, b2, b3;
                uint32_t adh = smem_u32(base + (p * 16 + kqr) * 72 + kc * 16 + kqc);
                LDSM_X4(b0, b1, b2, b3, adh);
                MMA16816H(acc[2 * p],     qhf[kc], b0, b1);
                MMA16816H(acc[2 * p + 1], qhf[kc], b2, b3);
            }
        }

        // bitmask + fixed-shift exp2; accumulate l locally
        const uint2 m0w = *(const uint2*)(mrow0 + 2 * kt);
        const uint2 m1w = *(const uint2*)(mrow1 + 2 * kt);
        #pragma unroll
        for (int hr = 0; hr < 2; hr++) {
            const int c0 = hr * 2, c1 = hr * 2 + 1;
            const uint2 mwd = hr ? m1w : m0w;
            float sum = 0.0f;
            #pragma unroll
            for (int nt = 0; nt < 8; nt++) {
                uint32_t w = (nt < 4) ? mwd.x : mwd.y;
                int shb = bsh + 8 * (nt & 3);
                float p0 = ((w >> shb) & 1u)       ? ex2f(acc[nt][c0] - SHIFT2) : 0.0f;
                float p1 = ((w >> (shb + 1)) & 1u) ? ex2f(acc[nt][c1] - SHIFT2) : 0.0f;
                acc[nt][c0] = p0; acc[nt][c1] = p1;
                sum += p0 + p1;
            }
            if (hr) l1 += sum; else l0 += sum;
        }

        // O += P @ (Vh + Vl): P single fp16, V hi/lo (2 MMA passes, same acc)
        #pragma unroll
        for (int j = 0; j < 4; j++) {
            uint32_t pf[4];
            pf[0] = pack_f16x2(acc[2 * j][0],     acc[2 * j][1]);
            pf[1] = pack_f16x2(acc[2 * j][2],     acc[2 * j][3]);
            pf[2] = pack_f16x2(acc[2 * j + 1][0], acc[2 * j + 1][1]);
            pf[3] = pack_f16x2(acc[2 * j + 1][2], acc[2 * j + 1][3]);
            #pragma unroll
            for (int pp = 0; pp < 4; pp++) {
                uint32_t vh0, vh1, vh2, vh3, vl0, vl1, vl2, vl3;
                uint32_t adh = smem_u32(base + FS_VH + (j * 16 + vbr) * 72 +
                                        pp * 16 + vbc);
                LDSM_X4_T(vh0, vh1, vh2, vh3, adh);
                uint32_t adl = smem_u32(base + FS_VL + (j * 16 + vbr) * 72 +
                                        pp * 16 + vbc);
                LDSM_X4_T(vl0, vl1, vl2, vl3, adl);
                MMA16816H(o[2 * pp],     pf, vh0, vh1);
                MMA16816H(o[2 * pp],     pf, vl0, vl1);
                MMA16816H(o[2 * pp + 1], pf, vh2, vh3);
                MMA16816H(o[2 * pp + 1], pf, vl2, vl3);
            }
        }
    }

    // Epilogue: reduce l across 4-lane group, normalize, split fp16 hi/lo
    l0 += __shfl_xor_sync(0xffffffffu, l0, 1);
    l0 += __shfl_xor_sync(0xffffffffu, l0, 2);
    l1 += __shfl_xor_sync(0xffffffffu, l1, 1);
    l1 += __shfl_xor_sync(0xffffffffu, l1, 2);
    const float inv0 = 1.0f / l0, inv1 = 1.0f / l1;
    const int grow0 = q0 + mw + r0;
    #pragma unroll
    for (int dt = 0; dt < 8; dt++) {
        int col = h * DK + dt * 8 + 2 * (lane & 3);
        size_t i0 = ((size_t)(b * SEQ + grow0)) * DMODEL + col;
        size_t i1 = ((size_t)(b * SEQ + grow0 + 8)) * DMODEL + col;
        uint32_t h32, l32;
        cvt_pfrag(o[dt][0] * inv0, o[dt][1] * inv0, h32, l32);
        *(uint32_t*)((unsigned short*)ch_g + i0) = h32;
        *(uint32_t*)((unsigned short*)cl_g + i0) = l32;
        cvt_pfrag(o[dt][2] * inv1, o[dt][3] * inv1, h32, l32);
        *(uint32_t*)((unsigned short*)ch_g + i1) = h32;
        *(uint32_t*)((unsigned short*)cl_g + i1) = l32;
    }
}

// ---------------------------------------------------------------------------
extern "C" void kernel_launch(void* const* d_in, const int* in_sizes, int n_in,
                              void* d_out, int out_size)
{
    const float* q    = (const float*)d_in[0];
    const float* k    = (const float*)d_in[1];
    const float* v    = (const float*)d_in[2];
    const int*   mask = (const int*)d_in[3];
    const float* Wq   = (const float*)d_in[4];
    const float* bq   = (const float*)d_in[5];
    const float* Wk   = (const float*)d_in[6];
    const float* bk   = (const float*)d_in[7];
    const float* Wv   = (const float*)d_in[8];
    const float* bv   = (const float*)d_in[9];
    const float* Wo   = (const float*)d_in[10];
    const float* bo   = (const float*)d_in[11];
    float* out = (float*)d_out;

    __half *qh, *kh, *vh, *vl, *ch2, *cl2;
    cudaGetSymbolAddress((void**)&qh, g_qh);
    cudaGetSymbolAddress((void**)&kh, g_kh);
    cudaGetSymbolAddress((void**)&vh, g_vh);
    cudaGetSymbolAddress((void**)&vl, g_vl);
    cudaGetSymbolAddress((void**)&ch2, g_ch2);
    cudaGetSymbolAddress((void**)&cl2, g_cl2);

    // Fused pre-convert + mask pack
    cvt_all<<<(ALL_T + 255) / 256, 256>>>(q, k, v, Wq, Wk, Wv, Wo, mask);

    const int gsmem = 3 * ST_SZ * 2;  // 87552 B
    cudaFuncSetAttribute(qkv_gemm, cudaFuncAttributeMaxDynamicSharedMemorySize, gsmem);
    cudaFuncSetAttribute(o_gemm, cudaFuncAttributeMaxDynamicSharedMemorySize, gsmem);

    qkv_gemm<<<dim3(8, 32, 3), 256, gsmem>>>(bq, bk, bv);

    const int fsmem = (FQ_SZ + 3 * FS_SZ) * 2;  // 101376 B
    cudaFuncSetAttribute(flash_tc,
                         cudaFuncAttributeMaxDynamicSharedMemorySize, fsmem);
    dim3 agrid(SEQ / 128, NHEADS, BATCH);
    flash_tc<<<agrid, 256, fsmem>>>(qh, kh, vh, vl, ch2, cl2);

    o_gemm<<<dim3(8, 32), 256, gsmem>>>(bo, out);
}